// round 11
// baseline (speedup 1.0000x reference)
#include <cuda_runtime.h>
#include <cuda_bf16.h>
#include <cstdint>
#include <cstddef>

#define CH   128
#define HH   96
#define WW   96
#define HW   9216          // 96*96
#define BATCH 16
#define NOUT 1000

// Padded mixed layout: data pixel (h,w) -> plane[(h+1)*PP + (w+2)]
// border cells (rows 0,97,98,99; cols 0,1,98,99) are zero -> maskless gather.
#define PP    104
#define PPH   100
#define PLANE (PP * PPH)   // 10400 floats per (b,c) plane

// ---------------------------------------------------------------------------
// Scratch (device globals — no runtime allocation allowed)
// ---------------------------------------------------------------------------
__device__ float g_mixed[(size_t)BATCH * CH * PLANE];   // 85.2 MB (padded)
__device__ float g_x[(size_t)BATCH * CH * HW];          // 75.5 MB
__device__ float g_pool[BATCH * CH];
// A fragments in mma register order: [slot][kstep(8)][mtile(8)][lane(32)]
__device__ uint4 g_afh[5 * 8 * 8 * 32];
__device__ uint4 g_afl[5 * 8 * 8 * 32];

// ---------------------------------------------------------------------------
__device__ __forceinline__ unsigned short bfbits(float x) {
    return __bfloat16_as_ushort(__float2bfloat16_rn(x));
}
__device__ __forceinline__ float bfval(float x) {
    return __bfloat162float(__float2bfloat16_rn(x));
}
__device__ __forceinline__ unsigned int pack2(unsigned short lo, unsigned short hi) {
    return (unsigned int)lo | ((unsigned int)hi << 16);
}
__device__ __forceinline__ void mma_bf16(float* d, uint4 a,
                                         unsigned int b0, unsigned int b1) {
    asm volatile(
        "mma.sync.aligned.m16n8k16.row.col.f32.bf16.bf16.f32 "
        "{%0,%1,%2,%3}, {%4,%5,%6,%7}, {%8,%9}, {%0,%1,%2,%3};"
        : "+f"(d[0]), "+f"(d[1]), "+f"(d[2]), "+f"(d[3])
        : "r"(a.x), "r"(a.y), "r"(a.z), "r"(a.w), "r"(b0), "r"(b1));
}

// ---------------------------------------------------------------------------
// prep_all: pack all 5 lin matrices into mma A-fragments (hi/lo bf16) in a
// single launch; also zeroes the pool accumulators.
// ---------------------------------------------------------------------------
__global__ void prep_all(const float* __restrict__ in_lin,
                         const float* __restrict__ lay_lin,
                         float* __restrict__ pool) {
    int t = blockIdx.x * 256 + threadIdx.x;
    if (t < BATCH * CH) pool[t] = 0.f;

    const float* lin;
    int slot, K, local;
    if (t < 1024) {
        slot = 0; K = 64; local = t; lin = in_lin;
    } else if (t < 1024 + 4 * 2048) {
        int j = t - 1024;
        slot = 1 + j / 2048; K = 128; local = j & 2047;
        lin = lay_lin + (size_t)(slot - 1) * CH * CH;
    } else return;

    int lane  = local & 31;
    int mtile = (local >> 5) & 7;
    int ks    = local >> 8;
    int m0 = mtile * 16 + (lane >> 2);
    int k0 = ks * 16 + (lane & 3) * 2;

    float a00 = lin[(size_t)m0 * K + k0],           a01 = lin[(size_t)m0 * K + k0 + 1];
    float a10 = lin[(size_t)(m0 + 8) * K + k0],     a11 = lin[(size_t)(m0 + 8) * K + k0 + 1];
    float a02 = lin[(size_t)m0 * K + k0 + 8],       a03 = lin[(size_t)m0 * K + k0 + 9];
    float a12 = lin[(size_t)(m0 + 8) * K + k0 + 8], a13 = lin[(size_t)(m0 + 8) * K + k0 + 9];

    uint4 h, l;
    h.x = pack2(bfbits(a00), bfbits(a01));
    h.y = pack2(bfbits(a10), bfbits(a11));
    h.z = pack2(bfbits(a02), bfbits(a03));
    h.w = pack2(bfbits(a12), bfbits(a13));
    l.x = pack2(bfbits(a00 - bfval(a00)), bfbits(a01 - bfval(a01)));
    l.y = pack2(bfbits(a10 - bfval(a10)), bfbits(a11 - bfval(a11)));
    l.z = pack2(bfbits(a02 - bfval(a02)), bfbits(a03 - bfval(a03)));
    l.w = pack2(bfbits(a12 - bfval(a12)), bfbits(a13 - bfval(a13)));

    int off = ((slot * 8 + ks) * 8 + mtile) * 32 + lane;
    g_afh[off] = h;
    g_afl[off] = l;
}

// ---------------------------------------------------------------------------
// border_init: zero the guard border of every padded mixed plane.
// ---------------------------------------------------------------------------
__global__ void border_init(float* __restrict__ m) {
    float* pl = m + (size_t)blockIdx.x * PLANE;
    for (int i = threadIdx.x; i < 4 * PP + 4 * 96; i += 128) {
        int idx;
        if (i < 4 * PP) {
            int r4 = i / PP;
            int rr = (r4 == 0) ? 0 : (96 + r4);
            idx = rr * PP + (i - r4 * PP);
        } else {
            int j  = i - 4 * PP;
            int c4 = j / 96;
            int col = (c4 < 2) ? c4 : (96 + c4);
            idx = (1 + (j - c4 * 96)) * PP + col;
        }
        pl[idx] = 0.f;
    }
}

// ---------------------------------------------------------------------------
// Tensor GEMM: mixed[b,c,p] = sum_i lin[c,i] * xin[b,i,p], bf16 hi/lo split
// (Ah*Bh + Ah*Bl + Al*Bh), fp32->bf16 conversion done in-kernel from the
// natural fp32 activation layout. Tile: M=128ch x N=64px, 8 warps (2m x 4n),
// full-K B tile in smem (pitch 72 -> conflict-free fragment LDS).
// ---------------------------------------------------------------------------
#define NPX    64
#define BPITCH 72
template<int K>
__global__ __launch_bounds__(256, 3)
void mix_gemm_mma(const float* __restrict__ xin,
                  float* __restrict__ outp, int slot) {
    constexpr int K2 = K / 2;
    constexpr int KS = K / 16;
    extern __shared__ unsigned int smb[];
    unsigned int* Bh = smb;
    unsigned int* Bl = smb + K2 * BPITCH;

    const int b     = blockIdx.y;
    const int pbase = blockIdx.x * NPX;
    const int tid   = threadIdx.x;
    const int lane  = tid & 31;
    const int warp  = tid >> 5;
    const int wm    = warp >> 2;   // 0..1  (M half)
    const int wn    = warp & 3;    // 0..3  (N quarter)

    // load fp32 activation tile, convert to hi/lo bf16 pair-packed smem
    {
        const float* xb = xin + (size_t)b * K * HW + pbase;
        for (int i = tid; i < K2 * NPX; i += 256) {
            int k2 = i >> 6, p = i & 63;
            float v0 = xb[(size_t)(2 * k2) * HW + p];
            float v1 = xb[(size_t)(2 * k2 + 1) * HW + p];
            unsigned short h0 = bfbits(v0), h1 = bfbits(v1);
            Bh[k2 * BPITCH + p] = pack2(h0, h1);
            Bl[k2 * BPITCH + p] = pack2(
                bfbits(v0 - __bfloat162float(__ushort_as_bfloat16(h0))),
                bfbits(v1 - __bfloat162float(__ushort_as_bfloat16(h1))));
        }
    }
    __syncthreads();

    float acc[4][2][4];
#pragma unroll
    for (int t = 0; t < 4; t++)
#pragma unroll
        for (int u = 0; u < 2; u++)
#pragma unroll
            for (int r = 0; r < 4; r++) acc[t][u][r] = 0.f;

    const uint4* afh = g_afh + (size_t)slot * 8 * 8 * 32;
    const uint4* afl = g_afl + (size_t)slot * 8 * 8 * 32;

#pragma unroll
    for (int ks = 0; ks < KS; ks++) {
        unsigned int bh0[2], bh1[2], bl0[2], bl1[2];
        const int r0 = (ks * 8 + (lane & 3)) * BPITCH;
        const int r1 = r0 + 4 * BPITCH;
#pragma unroll
        for (int u = 0; u < 2; u++) {
            int n = wn * 16 + u * 8 + (lane >> 2);
            bh0[u] = Bh[r0 + n]; bh1[u] = Bh[r1 + n];
            bl0[u] = Bl[r0 + n]; bl1[u] = Bl[r1 + n];
        }
#pragma unroll
        for (int t = 0; t < 4; t++) {
            uint4 ah = afh[(ks * 8 + wm * 4 + t) * 32 + lane];
            uint4 al = afl[(ks * 8 + wm * 4 + t) * 32 + lane];
#pragma unroll
            for (int u = 0; u < 2; u++) {
                mma_bf16(acc[t][u], ah, bh0[u], bh1[u]);
                mma_bf16(acc[t][u], ah, bl0[u], bl1[u]);
                mma_bf16(acc[t][u], al, bh0[u], bh1[u]);
            }
        }
    }

    float* mb = outp + (size_t)b * CH * PLANE;
#pragma unroll
    for (int t = 0; t < 4; t++) {
        int m0 = wm * 64 + t * 16 + (lane >> 2);
#pragma unroll
        for (int u = 0; u < 2; u++) {
            int p = pbase + wn * 16 + u * 8 + (lane & 3) * 2;
            int h = p / 96;
            int w = p - h * 96;
            size_t po = (size_t)(h + 1) * PP + (w + 2);
            *(float2*)(mb + (size_t)m0 * PLANE + po)       = make_float2(acc[t][u][0], acc[t][u][1]);
            *(float2*)(mb + (size_t)(m0 + 8) * PLANE + po) = make_float2(acc[t][u][2], acc[t][u][3]);
        }
    }
}

// ---------------------------------------------------------------------------
// Sample from padded mixed: maskless 4-tap gather (one coord clamp, zero
// border supplies out-of-range zeros), analytic box weight, residual add,
// optional fused avg-pool accumulation.
// grid: (36, CH, BATCH), 256 threads.
// ---------------------------------------------------------------------------
__global__ void sample_kernel(const float* __restrict__ mixedp,
                              const float* __restrict__ geo,
                              const float* __restrict__ box,
                              const float* __restrict__ resid,
                              float* __restrict__ out,
                              int do_pool,
                              float* __restrict__ pool) {
    const int c = blockIdx.y;
    const int b = blockIdx.z;
    const int p = blockIdx.x * 256 + threadIdx.x;
    const int h = p / WW;
    const int w = p - h * WW;

    const float gxc = (w + 0.5f) * (2.0f / WW) - 1.0f;
    const float gyc = (h + 0.5f) * (2.0f / HH) - 1.0f;

    const float* g = geo + c * 6;
    float ix = (__ldg(g + 0) * gxc + __ldg(g + 1) * gyc + __ldg(g + 2)) * 48.f + 47.5f;
    float iy = (__ldg(g + 3) * gxc + __ldg(g + 4) * gyc + __ldg(g + 5)) * 48.f + 47.5f;
    ix = fminf(fmaxf(ix, -1.0f), 96.0f);
    iy = fminf(fmaxf(iy, -1.0f), 96.0f);
    float fx0 = floorf(ix), fy0 = floorf(iy);
    int   x0 = (int)fx0, y0 = (int)fy0;
    float wx1 = ix - fx0, wy1 = iy - fy0;
    float wx0 = 1.0f - wx1, wy0 = 1.0f - wy1;

    const float* tapb = mixedp + ((size_t)b * CH + c) * PLANE
                      + (size_t)(y0 + 1) * PP + (x0 + 2);
    float t00 = tapb[0],  t01 = tapb[1];
    float t10 = tapb[PP], t11 = tapb[PP + 1];
    float s = wy0 * fmaf(wx0, t00, wx1 * t01)
            + wy1 * fmaf(wx0, t10, wx1 * t11);

    const float* bx = box + c * 6;
    float bix = (__ldg(bx + 0) * gxc + __ldg(bx + 1) * gyc + __ldg(bx + 2)) * 48.f + 47.5f;
    float biy = (__ldg(bx + 3) * gxc + __ldg(bx + 4) * gyc + __ldg(bx + 5)) * 48.f + 47.5f;
    float bfx0 = floorf(bix), bfy0 = floorf(biy);
    int   bx0 = (int)bfx0, by0 = (int)bfy0;
    float bwx1 = bix - bfx0, bwy1 = biy - bfy0;
    float sx = (((unsigned)bx0       < (unsigned)WW) ? (1.f - bwx1) : 0.f)
             + (((unsigned)(bx0 + 1) < (unsigned)WW) ? bwx1         : 0.f);
    float sy = (((unsigned)by0       < (unsigned)HH) ? (1.f - bwy1) : 0.f)
             + (((unsigned)(by0 + 1) < (unsigned)HH) ? bwy1         : 0.f);

    const size_t idx = ((size_t)b * CH + c) * HW + p;
    float v = s * (sx * sy);
    if (resid) v += resid[idx];
    out[idx] = v;

    if (do_pool) {
        float r = v;
        for (int o = 16; o > 0; o >>= 1) r += __shfl_down_sync(0xffffffffu, r, o);
        __shared__ float sm[8];
        if ((threadIdx.x & 31) == 0) sm[threadIdx.x >> 5] = r;
        __syncthreads();
        if (threadIdx.x == 0) {
            float tt = 0.f;
            for (int i = 0; i < 8; i++) tt += sm[i];
            atomicAdd(pool + b * CH + c, tt);
        }
    }
}

// ---------------------------------------------------------------------------
// Dense head (pool holds plane sums; fold the 1/HW mean here).
// ---------------------------------------------------------------------------
__global__ void dense_kernel(const float* __restrict__ pooled,
                             const float* __restrict__ dw,
                             const float* __restrict__ db,
                             float* __restrict__ logits) {
    int gid = blockIdx.x * 256 + threadIdx.x;
    if (gid >= BATCH * NOUT) return;
    int o = gid % NOUT;
    int b = gid / NOUT;
    const float* pr = pooled + b * CH;
    const float* wr = dw + (size_t)o * CH;
    float s = 0.f;
#pragma unroll 16
    for (int c = 0; c < CH; c++) s = fmaf(pr[c], wr[c], s);
    logits[gid] = s * (1.0f / HW) + db[o];
}

// ---------------------------------------------------------------------------
extern "C" void kernel_launch(void* const* d_in, const int* in_sizes, int n_in,
                              void* d_out, int out_size) {
    const float* x       = (const float*)d_in[0];
    const float* in_geo  = (const float*)d_in[1];
    const float* in_box  = (const float*)d_in[2];
    const float* in_lin  = (const float*)d_in[3];
    const float* lay_geo = (const float*)d_in[4];
    const float* lay_box = (const float*)d_in[5];
    const float* lay_lin = (const float*)d_in[6];
    const float* dense_w = (const float*)d_in[7];
    const float* dense_b = (const float*)d_in[8];

    float* out    = (float*)d_out;
    float* logits = out;
    float* feat   = out + BATCH * NOUT;

    float *mixed_p, *x_p, *pool_p;
    cudaGetSymbolAddress((void**)&mixed_p, g_mixed);
    cudaGetSymbolAddress((void**)&x_p,     g_x);
    cudaGetSymbolAddress((void**)&pool_p,  g_pool);

    const int smem64  = 2 * 32 * BPITCH * 4;   // 18432
    const int smem128 = 2 * 64 * BPITCH * 4;   // 36864 (< 48KB default)

    // prep: A fragments + pool zero (1 launch), border zeros
    prep_all<<<(1024 + 4 * 2048 + 255) / 256, 256>>>(in_lin, lay_lin, pool_p);
    border_init<<<BATCH * CH, 128>>>(mixed_p);

    dim3 ggrid(HW / NPX, BATCH);          // (144, 16)
    dim3 sgrid(HW / 256, CH, BATCH);      // (36, 128, 16)

    // input layer (K=64, no residual) — reads fp32 input directly
    mix_gemm_mma<64><<<ggrid, 256, smem64>>>(x, mixed_p, 0);
    sample_kernel<<<sgrid, 256>>>(mixed_p, in_geo, in_box, nullptr, x_p, 0, pool_p);

    // 4 residual layers (K=128)
    for (int i = 0; i < 4; i++) {
        mix_gemm_mma<128><<<ggrid, 256, smem128>>>(x_p, mixed_p, i + 1);
        bool last = (i == 3);
        float* dst = last ? feat : x_p;
        sample_kernel<<<sgrid, 256>>>(mixed_p, lay_geo + (size_t)i * CH * 6,
                                      lay_box + (size_t)i * CH * 6, x_p, dst,
                                      last ? 1 : 0, pool_p);
    }

    dense_kernel<<<(BATCH * NOUT + 255) / 256, 256>>>(pool_p, dense_w, dense_b, logits);
}

// round 12
// speedup vs baseline: 1.0531x; 1.0531x over previous
#include <cuda_runtime.h>
#include <cuda_bf16.h>
#include <cstdint>
#include <cstddef>

#define CH   128
#define HH   96
#define WW   96
#define HW   9216          // 96*96
#define BATCH 16
#define NOUT 1000

// ---------------------------------------------------------------------------
// Scratch (device globals — no runtime allocation allowed)
// ---------------------------------------------------------------------------
__device__ float g_mixed[(size_t)BATCH * CH * HW];      // 75.5 MB
__device__ float g_x[(size_t)BATCH * CH * HW];          // 75.5 MB
__device__ float g_pool[BATCH * CH];
// planar bf16 hi/lo activation planes: [b][k][HW] ushort
__device__ unsigned short g_pbh[(size_t)BATCH * CH * HW];  // 37.75 MB
__device__ unsigned short g_pbl[(size_t)BATCH * CH * HW];  // 37.75 MB
// A fragments in mma register order: [slot][kstep(8)][mtile(8)][lane(32)]
__device__ uint4 g_afh[5 * 8 * 8 * 32];
__device__ uint4 g_afl[5 * 8 * 8 * 32];

// ---------------------------------------------------------------------------
__device__ __forceinline__ unsigned short bfbits(float x) {
    return __bfloat16_as_ushort(__float2bfloat16_rn(x));
}
__device__ __forceinline__ float bfval(float x) {
    return __bfloat162float(__float2bfloat16_rn(x));
}
__device__ __forceinline__ unsigned int pack2(unsigned short lo, unsigned short hi) {
    return (unsigned int)lo | ((unsigned int)hi << 16);
}
__device__ __forceinline__ void mma_bf16(float* d, uint4 a,
                                         unsigned int b0, unsigned int b1) {
    asm volatile(
        "mma.sync.aligned.m16n8k16.row.col.f32.bf16.bf16.f32 "
        "{%0,%1,%2,%3}, {%4,%5,%6,%7}, {%8,%9}, {%0,%1,%2,%3};"
        : "+f"(d[0]), "+f"(d[1]), "+f"(d[2]), "+f"(d[3])
        : "r"(a.x), "r"(a.y), "r"(a.z), "r"(a.w), "r"(b0), "r"(b1));
}

// ---------------------------------------------------------------------------
// prep_all: pack all 5 lin matrices into mma A-fragments (hi/lo bf16) in
// ONE launch (replaces 5 prep_A launches, 4.4us idle each).
// ---------------------------------------------------------------------------
__global__ void prep_all(const float* __restrict__ in_lin,
                         const float* __restrict__ lay_lin) {
    int t = blockIdx.x * 256 + threadIdx.x;

    const float* lin;
    int slot, K, local;
    if (t < 1024) {
        slot = 0; K = 64; local = t; lin = in_lin;
    } else if (t < 1024 + 4 * 2048) {
        int j = t - 1024;
        slot = 1 + j / 2048; K = 128; local = j & 2047;
        lin = lay_lin + (size_t)(slot - 1) * CH * CH;
    } else return;

    int lane  = local & 31;
    int mtile = (local >> 5) & 7;
    int ks    = local >> 8;
    int m0 = mtile * 16 + (lane >> 2);
    int k0 = ks * 16 + (lane & 3) * 2;

    float a00 = lin[(size_t)m0 * K + k0],           a01 = lin[(size_t)m0 * K + k0 + 1];
    float a10 = lin[(size_t)(m0 + 8) * K + k0],     a11 = lin[(size_t)(m0 + 8) * K + k0 + 1];
    float a02 = lin[(size_t)m0 * K + k0 + 8],       a03 = lin[(size_t)m0 * K + k0 + 9];
    float a12 = lin[(size_t)(m0 + 8) * K + k0 + 8], a13 = lin[(size_t)(m0 + 8) * K + k0 + 9];

    uint4 h, l;
    h.x = pack2(bfbits(a00), bfbits(a01));
    h.y = pack2(bfbits(a10), bfbits(a11));
    h.z = pack2(bfbits(a02), bfbits(a03));
    h.w = pack2(bfbits(a12), bfbits(a13));
    l.x = pack2(bfbits(a00 - bfval(a00)), bfbits(a01 - bfval(a01)));
    l.y = pack2(bfbits(a10 - bfval(a10)), bfbits(a11 - bfval(a11)));
    l.z = pack2(bfbits(a02 - bfval(a02)), bfbits(a03 - bfval(a03)));
    l.w = pack2(bfbits(a12 - bfval(a12)), bfbits(a13 - bfval(a13)));

    int off = ((slot * 8 + ks) * 8 + mtile) * 32 + lane;
    g_afh[off] = h;
    g_afl[off] = l;
}

// ---------------------------------------------------------------------------
// convert_in: x fp32 [16,64,HW] -> planar bf16 hi/lo ushort planes
// ---------------------------------------------------------------------------
__global__ void convert_in(const float* __restrict__ x,
                           unsigned short* __restrict__ pbh,
                           unsigned short* __restrict__ pbl) {
    size_t t = (size_t)blockIdx.x * 256 + threadIdx.x;  // 16*64*2304
    if (t >= (size_t)BATCH * 64 * (HW / 4)) return;
    const float4 v = *(const float4*)(x + t * 4);
    unsigned short h0 = bfbits(v.x), h1 = bfbits(v.y);
    unsigned short h2 = bfbits(v.z), h3 = bfbits(v.w);
    uint2 hh, ll;
    hh.x = pack2(h0, h1); hh.y = pack2(h2, h3);
    ll.x = pack2(bfbits(v.x - __bfloat162float(__ushort_as_bfloat16(h0))),
                 bfbits(v.y - __bfloat162float(__ushort_as_bfloat16(h1))));
    ll.y = pack2(bfbits(v.z - __bfloat162float(__ushort_as_bfloat16(h2))),
                 bfbits(v.w - __bfloat162float(__ushort_as_bfloat16(h3))));
    *(uint2*)(pbh + t * 4) = hh;
    *(uint2*)(pbl + t * 4) = ll;
}

// ---------------------------------------------------------------------------
// Tensor GEMM (R9 measured-best shape): mixed[b,c,p] = sum_i lin[c,i]*x[b,i,p]
// Block: 128ch x 128px, 8 warps (2m x 4n), full-K B tile in smem (pitch 136).
// B loader re-pairs planar rows 2k2 / 2k2+1 via byte_perm.
// ---------------------------------------------------------------------------
#define BPITCH 136
template<int K>
__global__ __launch_bounds__(256, 2)
void mix_gemm_mma(const unsigned short* __restrict__ pbh,
                  const unsigned short* __restrict__ pbl,
                  float* __restrict__ out, int slot) {
    constexpr int K2 = K / 2;
    constexpr int KS = K / 16;
    extern __shared__ unsigned int smb[];
    unsigned int* Bh = smb;
    unsigned int* Bl = smb + K2 * BPITCH;

    const int b     = blockIdx.y;
    const int pbase = blockIdx.x * 128;
    const int tid   = threadIdx.x;
    const int lane  = tid & 31;
    const int warp  = tid >> 5;
    const int wm    = warp >> 2;   // 0..1
    const int wn    = warp & 3;    // 0..3

    // load planar bf16 rows, pair-pack into smem: entry(k2,p) = (ch2k2, ch2k2+1)
    {
        const unsigned short* gh = pbh + (size_t)b * K * HW + pbase;
        const unsigned short* gl = pbl + (size_t)b * K * HW + pbase;
        for (int i = tid; i < K2 * 64; i += 256) {
            int k2 = i >> 6, p2 = i & 63;           // p2: pixel pair index
            unsigned int h0 = *(const unsigned int*)(gh + (size_t)(2 * k2) * HW + 2 * p2);
            unsigned int h1 = *(const unsigned int*)(gh + (size_t)(2 * k2 + 1) * HW + 2 * p2);
            unsigned int l0 = *(const unsigned int*)(gl + (size_t)(2 * k2) * HW + 2 * p2);
            unsigned int l1 = *(const unsigned int*)(gl + (size_t)(2 * k2 + 1) * HW + 2 * p2);
            *(uint2*)&Bh[k2 * BPITCH + 2 * p2] =
                make_uint2(__byte_perm(h0, h1, 0x5410), __byte_perm(h0, h1, 0x7632));
            *(uint2*)&Bl[k2 * BPITCH + 2 * p2] =
                make_uint2(__byte_perm(l0, l1, 0x5410), __byte_perm(l0, l1, 0x7632));
        }
    }
    __syncthreads();

    float acc[4][4][4];
#pragma unroll
    for (int t = 0; t < 4; t++)
#pragma unroll
        for (int u = 0; u < 4; u++)
#pragma unroll
            for (int r = 0; r < 4; r++) acc[t][u][r] = 0.f;

    const uint4* afh = g_afh + (size_t)slot * 8 * 8 * 32;
    const uint4* afl = g_afl + (size_t)slot * 8 * 8 * 32;

#pragma unroll
    for (int ks = 0; ks < KS; ks++) {
        unsigned int bh0[4], bh1[4], bl0[4], bl1[4];
        const int r0 = (ks * 8 + (lane & 3)) * BPITCH;
        const int r1 = r0 + 4 * BPITCH;
#pragma unroll
        for (int u = 0; u < 4; u++) {
            int n = wn * 32 + u * 8 + (lane >> 2);
            bh0[u] = Bh[r0 + n]; bh1[u] = Bh[r1 + n];
            bl0[u] = Bl[r0 + n]; bl1[u] = Bl[r1 + n];
        }
#pragma unroll
        for (int t = 0; t < 4; t++) {
            uint4 ah = afh[(ks * 8 + wm * 4 + t) * 32 + lane];
            uint4 al = afl[(ks * 8 + wm * 4 + t) * 32 + lane];
#pragma unroll
            for (int u = 0; u < 4; u++) {
                mma_bf16(acc[t][u], ah, bh0[u], bh1[u]);
                mma_bf16(acc[t][u], ah, bl0[u], bl1[u]);
                mma_bf16(acc[t][u], al, bh0[u], bh1[u]);
            }
        }
    }

    float* ob = out + (size_t)b * CH * HW + pbase;
#pragma unroll
    for (int t = 0; t < 4; t++) {
        int m0 = wm * 64 + t * 16 + (lane >> 2);
#pragma unroll
        for (int u = 0; u < 4; u++) {
            int n0 = wn * 32 + u * 8 + (lane & 3) * 2;
            *(float2*)(ob + (size_t)m0 * HW + n0)       = make_float2(acc[t][u][0], acc[t][u][1]);
            *(float2*)(ob + (size_t)(m0 + 8) * HW + n0) = make_float2(acc[t][u][2], acc[t][u][3]);
        }
    }
}

// ---------------------------------------------------------------------------
// Sample (R9 measured-best structure) + coalesced planar bf16 hi/lo emit.
// grid: (36, CH, BATCH), 256 threads (one output pixel each).
// ---------------------------------------------------------------------------
__global__ void sample_kernel(const float* __restrict__ mixed,
                              const float* __restrict__ geo,
                              const float* __restrict__ box,
                              const float* __restrict__ resid,
                              float* __restrict__ out,
                              unsigned short* __restrict__ pbh,
                              unsigned short* __restrict__ pbl) {
    const int c = blockIdx.y;
    const int b = blockIdx.z;
    const int p = blockIdx.x * 256 + threadIdx.x;
    const int h = p / WW;
    const int w = p - h * WW;

    const float gxc = (w + 0.5f) * (2.0f / WW) - 1.0f;
    const float gyc = (h + 0.5f) * (2.0f / HH) - 1.0f;

    const float* g = geo + c * 6;
    float gridx = g[0] * gxc + g[1] * gyc + g[2];
    float gridy = g[3] * gxc + g[4] * gyc + g[5];
    float ix = ((gridx + 1.0f) * WW - 1.0f) * 0.5f;
    float iy = ((gridy + 1.0f) * HH - 1.0f) * 0.5f;
    float fx0 = floorf(ix), fy0 = floorf(iy);
    int   x0 = (int)fx0, y0 = (int)fy0;
    float wx1 = ix - fx0, wy1 = iy - fy0;
    float wx0 = 1.0f - wx1, wy0 = 1.0f - wy1;

    const float* plane = mixed + ((size_t)b * CH + c) * HW;
    auto tap = [&](int yi, int xi, float wt) -> float {
        bool v = (xi >= 0) & (xi < WW) & (yi >= 0) & (yi < HH);
        int xc = min(max(xi, 0), WW - 1);
        int yc = min(max(yi, 0), HH - 1);
        return v ? plane[yc * WW + xc] * wt : 0.0f;
    };
    float s = tap(y0,     x0,     wy0 * wx0)
            + tap(y0,     x0 + 1, wy0 * wx1)
            + tap(y0 + 1, x0,     wy1 * wx0)
            + tap(y0 + 1, x0 + 1, wy1 * wx1);

    const float* bx = box + c * 6;
    float bgx = bx[0] * gxc + bx[1] * gyc + bx[2];
    float bgy = bx[3] * gxc + bx[4] * gyc + bx[5];
    float bix = ((bgx + 1.0f) * WW - 1.0f) * 0.5f;
    float biy = ((bgy + 1.0f) * HH - 1.0f) * 0.5f;
    float bfx0 = floorf(bix), bfy0 = floorf(biy);
    int   bx0 = (int)bfx0, by0 = (int)bfy0;
    float bwx1 = bix - bfx0, bwy1 = biy - bfy0;
    float bwx0 = 1.0f - bwx1, bwy0 = 1.0f - bwy1;

    auto vmask = [](int yi, int xi) -> float {
        return ((xi >= 0) & (xi < WW) & (yi >= 0) & (yi < HH)) ? 1.0f : 0.0f;
    };
    float bval = vmask(by0,     bx0)     * bwy0 * bwx0
               + vmask(by0,     bx0 + 1) * bwy0 * bwx1
               + vmask(by0 + 1, bx0)     * bwy1 * bwx0
               + vmask(by0 + 1, bx0 + 1) * bwy1 * bwx1;

    const size_t idx = ((size_t)b * CH + c) * HW + p;
    float v = s * bval;
    if (resid) v += resid[idx];
    out[idx] = v;

    if (pbh) {
        unsigned short hb = bfbits(v);
        unsigned short lb = bfbits(v - __bfloat162float(__ushort_as_bfloat16(hb)));
        pbh[idx] = hb;   // planar: fully coalesced 2B stores
        pbl[idx] = lb;
    }
}

// ---------------------------------------------------------------------------
__global__ void pool_kernel(const float* __restrict__ feat,
                            float* __restrict__ pooled) {
    const int bc = blockIdx.x;
    const float* plane = feat + (size_t)bc * HW;
    float s = 0.f;
    for (int i = threadIdx.x; i < HW / 4; i += 256) {
        float4 v = *(const float4*)(plane + i * 4);
        s += (v.x + v.y) + (v.z + v.w);
    }
    for (int o = 16; o > 0; o >>= 1) s += __shfl_down_sync(0xffffffffu, s, o);
    __shared__ float sm[8];
    if ((threadIdx.x & 31) == 0) sm[threadIdx.x >> 5] = s;
    __syncthreads();
    if (threadIdx.x == 0) {
        float t = 0.f;
        for (int i = 0; i < 8; i++) t += sm[i];
        pooled[bc] = t * (1.0f / HW);
    }
}

__global__ void dense_kernel(const float* __restrict__ pooled,
                             const float* __restrict__ dw,
                             const float* __restrict__ db,
                             float* __restrict__ logits) {
    int gid = blockIdx.x * 256 + threadIdx.x;
    if (gid >= BATCH * NOUT) return;
    int o = gid % NOUT;
    int b = gid / NOUT;
    const float* pr = pooled + b * CH;
    const float* wr = dw + (size_t)o * CH;
    float s = 0.f;
#pragma unroll 16
    for (int c = 0; c < CH; c++) s = fmaf(pr[c], wr[c], s);
    logits[gid] = s + db[o];
}

// ---------------------------------------------------------------------------
extern "C" void kernel_launch(void* const* d_in, const int* in_sizes, int n_in,
                              void* d_out, int out_size) {
    const float* x       = (const float*)d_in[0];
    const float* in_geo  = (const float*)d_in[1];
    const float* in_box  = (const float*)d_in[2];
    const float* in_lin  = (const float*)d_in[3];
    const float* lay_geo = (const float*)d_in[4];
    const float* lay_box = (const float*)d_in[5];
    const float* lay_lin = (const float*)d_in[6];
    const float* dense_w = (const float*)d_in[7];
    const float* dense_b = (const float*)d_in[8];

    float* out    = (float*)d_out;
    float* logits = out;
    float* feat   = out + BATCH * NOUT;

    float *mixed_p, *x_p, *pool_p;
    unsigned short *pbh_p, *pbl_p;
    cudaGetSymbolAddress((void**)&mixed_p, g_mixed);
    cudaGetSymbolAddress((void**)&x_p,     g_x);
    cudaGetSymbolAddress((void**)&pool_p,  g_pool);
    cudaGetSymbolAddress((void**)&pbh_p,   g_pbh);
    cudaGetSymbolAddress((void**)&pbl_p,   g_pbl);

    const int smem64  = 2 * 32 * BPITCH * 4;   // 34816
    const int smem128 = 2 * 64 * BPITCH * 4;   // 69632
    static bool attr_done = false;
    if (!attr_done) {
        cudaFuncSetAttribute(mix_gemm_mma<64>,  cudaFuncAttributeMaxDynamicSharedMemorySize, smem64);
        cudaFuncSetAttribute(mix_gemm_mma<128>, cudaFuncAttributeMaxDynamicSharedMemorySize, smem128);
        attr_done = true;
    }

    // prep: A fragments (1 launch) + input bf16 conversion
    prep_all<<<(1024 + 4 * 2048 + 255) / 256, 256>>>(in_lin, lay_lin);
    convert_in<<<(BATCH * 64 * (HW / 4) + 255) / 256, 256>>>(x, pbh_p, pbl_p);

    dim3 ggrid(HW / 128, BATCH);          // (72, 16)
    dim3 sgrid(HW / 256, CH, BATCH);      // (36, 128, 16)

    // input layer (K=64, no residual); sample emits bf16 for next GEMM
    mix_gemm_mma<64><<<ggrid, 256, smem64>>>(pbh_p, pbl_p, mixed_p, 0);
    sample_kernel<<<sgrid, 256>>>(mixed_p, in_geo, in_box, nullptr, x_p, pbh_p, pbl_p);

    // 4 residual layers (K=128)
    for (int i = 0; i < 4; i++) {
        mix_gemm_mma<128><<<ggrid, 256, smem128>>>(pbh_p, pbl_p, mixed_p, i + 1);
        bool last = (i == 3);
        float* dst = last ? feat : x_p;
        sample_kernel<<<sgrid, 256>>>(mixed_p, lay_geo + (size_t)i * CH * 6,
                                      lay_box + (size_t)i * CH * 6, x_p, dst,
                                      last ? nullptr : pbh_p,
                                      last ? nullptr : pbl_p);
    }

    pool_kernel<<<BATCH * CH, 256>>>(feat, pool_p);
    dense_kernel<<<(BATCH * NOUT + 255) / 256, 256>>>(pool_p, dense_w, dense_b, logits);
}

// round 13
// speedup vs baseline: 1.1275x; 1.0706x over previous
#include <cuda_runtime.h>
#include <cuda_bf16.h>
#include <cstdint>
#include <cstddef>

#define CH   128
#define HH   96
#define WW   96
#define HW   9216          // 96*96
#define BATCH 16
#define NOUT 1000

// Padded mixed layout: data pixel (h,w) -> plane[(h+1)*PP + (w+2)]
// border cells (rows 0,97..99; cols 0,1,98,99) stay zero -> maskless gather.
#define PP    104
#define PPH   100
#define PLANE (PP * PPH)   // 10400 floats per (b,c) plane

// ---------------------------------------------------------------------------
// Scratch (device globals — no runtime allocation allowed)
// ---------------------------------------------------------------------------
__device__ float g_mixed[(size_t)BATCH * CH * PLANE];   // 85.2 MB (padded)
__device__ float g_x[(size_t)BATCH * CH * HW];          // 75.5 MB
__device__ float g_pool[BATCH * CH];
// A fragments in mma register order: [slot][kstep(8)][mtile(8)][lane(32)]
__device__ uint4 g_afh[5 * 8 * 8 * 32];
__device__ uint4 g_afl[5 * 8 * 8 * 32];

// ---------------------------------------------------------------------------
__device__ __forceinline__ unsigned short bfbits(float x) {
    return __bfloat16_as_ushort(__float2bfloat16_rn(x));
}
__device__ __forceinline__ float bfval(float x) {
    return __bfloat162float(__float2bfloat16_rn(x));
}
__device__ __forceinline__ unsigned int pack2(unsigned short lo, unsigned short hi) {
    return (unsigned int)lo | ((unsigned int)hi << 16);
}
__device__ __forceinline__ void mma_bf16(float* d, uint4 a,
                                         unsigned int b0, unsigned int b1) {
    asm volatile(
        "mma.sync.aligned.m16n8k16.row.col.f32.bf16.bf16.f32 "
        "{%0,%1,%2,%3}, {%4,%5,%6,%7}, {%8,%9}, {%0,%1,%2,%3};"
        : "+f"(d[0]), "+f"(d[1]), "+f"(d[2]), "+f"(d[3])
        : "r"(a.x), "r"(a.y), "r"(a.z), "r"(a.w), "r"(b0), "r"(b1));
}

// ---------------------------------------------------------------------------
// prep_all: pack all 5 lin matrices into mma A-fragments (hi/lo bf16) in one
// launch; also zeroes the pool accumulators.
// ---------------------------------------------------------------------------
__global__ void prep_all(const float* __restrict__ in_lin,
                         const float* __restrict__ lay_lin,
                         float* __restrict__ pool) {
    int t = blockIdx.x * 256 + threadIdx.x;
    if (t < BATCH * CH) pool[t] = 0.f;

    const float* lin;
    int slot, K, local;
    if (t < 1024) {
        slot = 0; K = 64; local = t; lin = in_lin;
    } else if (t < 1024 + 4 * 2048) {
        int j = t - 1024;
        slot = 1 + j / 2048; K = 128; local = j & 2047;
        lin = lay_lin + (size_t)(slot - 1) * CH * CH;
    } else return;

    int lane  = local & 31;
    int mtile = (local >> 5) & 7;
    int ks    = local >> 8;
    int m0 = mtile * 16 + (lane >> 2);
    int k0 = ks * 16 + (lane & 3) * 2;

    float a00 = lin[(size_t)m0 * K + k0],           a01 = lin[(size_t)m0 * K + k0 + 1];
    float a10 = lin[(size_t)(m0 + 8) * K + k0],     a11 = lin[(size_t)(m0 + 8) * K + k0 + 1];
    float a02 = lin[(size_t)m0 * K + k0 + 8],       a03 = lin[(size_t)m0 * K + k0 + 9];
    float a12 = lin[(size_t)(m0 + 8) * K + k0 + 8], a13 = lin[(size_t)(m0 + 8) * K + k0 + 9];

    uint4 h, l;
    h.x = pack2(bfbits(a00), bfbits(a01));
    h.y = pack2(bfbits(a10), bfbits(a11));
    h.z = pack2(bfbits(a02), bfbits(a03));
    h.w = pack2(bfbits(a12), bfbits(a13));
    l.x = pack2(bfbits(a00 - bfval(a00)), bfbits(a01 - bfval(a01)));
    l.y = pack2(bfbits(a10 - bfval(a10)), bfbits(a11 - bfval(a11)));
    l.z = pack2(bfbits(a02 - bfval(a02)), bfbits(a03 - bfval(a03)));
    l.w = pack2(bfbits(a12 - bfval(a12)), bfbits(a13 - bfval(a13)));

    int off = ((slot * 8 + ks) * 8 + mtile) * 32 + lane;
    g_afh[off] = h;
    g_afl[off] = l;
}

// ---------------------------------------------------------------------------
// border_init: zero the guard border of every padded mixed plane (GEMM writes
// only the interior, so borders stay zero for the whole run).
// ---------------------------------------------------------------------------
__global__ void border_init(float* __restrict__ m) {
    float* pl = m + (size_t)blockIdx.x * PLANE;
    for (int i = threadIdx.x; i < 4 * PP + 4 * 96; i += 128) {
        int idx;
        if (i < 4 * PP) {
            int r4 = i / PP;
            int rr = (r4 == 0) ? 0 : (96 + r4);     // rows 0,97,98,99
            idx = rr * PP + (i - r4 * PP);
        } else {
            int j  = i - 4 * PP;
            int c4 = j / 96;
            int col = (c4 < 2) ? c4 : (96 + c4);    // cols 0,1,98,99
            idx = (1 + (j - c4 * 96)) * PP + col;   // rows 1..96
        }
        pl[idx] = 0.f;
    }
}

// ---------------------------------------------------------------------------
// Tensor GEMM (R9 measured-best shape, fp32-direct loader):
// mixed[b,c,p] = sum_i lin[c,i] * xin[b,i,p] via bf16 hi/lo split
// (Ah*Bh + Ah*Bl + Al*Bh). Block: 128ch x 128px, 8 warps (2m x 4n),
// full-K B tile in smem (pitch 136 -> conflict-free fragment LDS).
// Loader reads natural fp32 activations and converts in-kernel.
// Epilogue writes padded mixed planes.
// ---------------------------------------------------------------------------
#define BPITCH 136
template<int K>
__global__ __launch_bounds__(256, 2)
void mix_gemm_mma(const float* __restrict__ xin,
                  float* __restrict__ outp, int slot) {
    constexpr int K2 = K / 2;
    constexpr int KS = K / 16;
    extern __shared__ unsigned int smb[];
    unsigned int* Bh = smb;
    unsigned int* Bl = smb + K2 * BPITCH;

    const int b     = blockIdx.y;
    const int pbase = blockIdx.x * 128;
    const int tid   = threadIdx.x;
    const int lane  = tid & 31;
    const int warp  = tid >> 5;
    const int wm    = warp >> 2;   // 0..1
    const int wn    = warp & 3;    // 0..3

    // fp32 load + hi/lo bf16 pair-pack: entry(k2,p) = (ch 2k2, ch 2k2+1)
    {
        const float* xb = xin + (size_t)b * K * HW + pbase;
        for (int i = tid; i < K2 * 128; i += 256) {
            int k2 = i >> 7, p = i & 127;
            float v0 = xb[(size_t)(2 * k2) * HW + p];
            float v1 = xb[(size_t)(2 * k2 + 1) * HW + p];
            unsigned short h0 = bfbits(v0), h1 = bfbits(v1);
            Bh[k2 * BPITCH + p] = pack2(h0, h1);
            Bl[k2 * BPITCH + p] = pack2(
                bfbits(v0 - __bfloat162float(__ushort_as_bfloat16(h0))),
                bfbits(v1 - __bfloat162float(__ushort_as_bfloat16(h1))));
        }
    }
    __syncthreads();

    float acc[4][4][4];
#pragma unroll
    for (int t = 0; t < 4; t++)
#pragma unroll
        for (int u = 0; u < 4; u++)
#pragma unroll
            for (int r = 0; r < 4; r++) acc[t][u][r] = 0.f;

    const uint4* afh = g_afh + (size_t)slot * 8 * 8 * 32;
    const uint4* afl = g_afl + (size_t)slot * 8 * 8 * 32;

#pragma unroll
    for (int ks = 0; ks < KS; ks++) {
        unsigned int bh0[4], bh1[4], bl0[4], bl1[4];
        const int r0 = (ks * 8 + (lane & 3)) * BPITCH;
        const int r1 = r0 + 4 * BPITCH;
#pragma unroll
        for (int u = 0; u < 4; u++) {
            int n = wn * 32 + u * 8 + (lane >> 2);
            bh0[u] = Bh[r0 + n]; bh1[u] = Bh[r1 + n];
            bl0[u] = Bl[r0 + n]; bl1[u] = Bl[r1 + n];
        }
#pragma unroll
        for (int t = 0; t < 4; t++) {
            uint4 ah = afh[(ks * 8 + wm * 4 + t) * 32 + lane];
            uint4 al = afl[(ks * 8 + wm * 4 + t) * 32 + lane];
#pragma unroll
            for (int u = 0; u < 4; u++) {
                mma_bf16(acc[t][u], ah, bh0[u], bh1[u]);
                mma_bf16(acc[t][u], ah, bl0[u], bl1[u]);
                mma_bf16(acc[t][u], al, bh0[u], bh1[u]);
            }
        }
    }

    // epilogue -> padded planes (measured free vs unpadded in R10)
    float* mb = outp + (size_t)b * CH * PLANE;
#pragma unroll
    for (int t = 0; t < 4; t++) {
        int m0 = wm * 64 + t * 16 + (lane >> 2);
#pragma unroll
        for (int u = 0; u < 4; u++) {
            int p = pbase + wn * 32 + u * 8 + (lane & 3) * 2;
            int h = p / 96;
            int w = p - h * 96;
            size_t po = (size_t)(h + 1) * PP + (w + 2);
            *(float2*)(mb + (size_t)m0 * PLANE + po)       = make_float2(acc[t][u][0], acc[t][u][1]);
            *(float2*)(mb + (size_t)(m0 + 8) * PLANE + po) = make_float2(acc[t][u][2], acc[t][u][3]);
        }
    }
}

// ---------------------------------------------------------------------------
// Sample from padded mixed (R11 measured-best, 79us): maskless 4-tap gather
// (single coord clamp; zero border supplies out-of-range zeros), analytic box
// weight, residual add, optional fused avg-pool accumulation.
// grid: (36, CH, BATCH), 256 threads.
// ---------------------------------------------------------------------------
__global__ void sample_kernel(const float* __restrict__ mixedp,
                              const float* __restrict__ geo,
                              const float* __restrict__ box,
                              const float* __restrict__ resid,
                              float* __restrict__ out,
                              int do_pool,
                              float* __restrict__ pool) {
    const int c = blockIdx.y;
    const int b = blockIdx.z;
    const int p = blockIdx.x * 256 + threadIdx.x;
    const int h = p / WW;
    const int w = p - h * WW;

    const float gxc = (w + 0.5f) * (2.0f / WW) - 1.0f;
    const float gyc = (h + 0.5f) * (2.0f / HH) - 1.0f;

    const float* g = geo + c * 6;
    float ix = (__ldg(g + 0) * gxc + __ldg(g + 1) * gyc + __ldg(g + 2)) * 48.f + 47.5f;
    float iy = (__ldg(g + 3) * gxc + __ldg(g + 4) * gyc + __ldg(g + 5)) * 48.f + 47.5f;
    ix = fminf(fmaxf(ix, -1.0f), 96.0f);
    iy = fminf(fmaxf(iy, -1.0f), 96.0f);
    float fx0 = floorf(ix), fy0 = floorf(iy);
    int   x0 = (int)fx0, y0 = (int)fy0;
    float wx1 = ix - fx0, wy1 = iy - fy0;
    float wx0 = 1.0f - wx1, wy0 = 1.0f - wy1;

    const float* tapb = mixedp + ((size_t)b * CH + c) * PLANE
                      + (size_t)(y0 + 1) * PP + (x0 + 2);
    float t00 = tapb[0],  t01 = tapb[1];
    float t10 = tapb[PP], t11 = tapb[PP + 1];
    float s = wy0 * fmaf(wx0, t00, wx1 * t01)
            + wy1 * fmaf(wx0, t10, wx1 * t11);

    const float* bx = box + c * 6;
    float bix = (__ldg(bx + 0) * gxc + __ldg(bx + 1) * gyc + __ldg(bx + 2)) * 48.f + 47.5f;
    float biy = (__ldg(bx + 3) * gxc + __ldg(bx + 4) * gyc + __ldg(bx + 5)) * 48.f + 47.5f;
    float bfx0 = floorf(bix), bfy0 = floorf(biy);
    int   bx0 = (int)bfx0, by0 = (int)bfy0;
    float bwx1 = bix - bfx0, bwy1 = biy - bfy0;
    float sx = (((unsigned)bx0       < (unsigned)WW) ? (1.f - bwx1) : 0.f)
             + (((unsigned)(bx0 + 1) < (unsigned)WW) ? bwx1         : 0.f);
    float sy = (((unsigned)by0       < (unsigned)HH) ? (1.f - bwy1) : 0.f)
             + (((unsigned)(by0 + 1) < (unsigned)HH) ? bwy1         : 0.f);

    const size_t idx = ((size_t)b * CH + c) * HW + p;
    float v = s * (sx * sy);
    if (resid) v += resid[idx];
    out[idx] = v;

    if (do_pool) {
        float r = v;
        for (int o = 16; o > 0; o >>= 1) r += __shfl_down_sync(0xffffffffu, r, o);
        __shared__ float sm[8];
        if ((threadIdx.x & 31) == 0) sm[threadIdx.x >> 5] = r;
        __syncthreads();
        if (threadIdx.x == 0) {
            float tt = 0.f;
            for (int i = 0; i < 8; i++) tt += sm[i];
            atomicAdd(pool + b * CH + c, tt);
        }
    }
}

// ---------------------------------------------------------------------------
// Dense head (pool holds plane sums; fold the 1/HW mean here).
// ---------------------------------------------------------------------------
__global__ void dense_kernel(const float* __restrict__ pooled,
                             const float* __restrict__ dw,
                             const float* __restrict__ db,
                             float* __restrict__ logits) {
    int gid = blockIdx.x * 256 + threadIdx.x;
    if (gid >= BATCH * NOUT) return;
    int o = gid % NOUT;
    int b = gid / NOUT;
    const float* pr = pooled + b * CH;
    const float* wr = dw + (size_t)o * CH;
    float s = 0.f;
#pragma unroll 16
    for (int c = 0; c < CH; c++) s = fmaf(pr[c], wr[c], s);
    logits[gid] = s * (1.0f / HW) + db[o];
}

// ---------------------------------------------------------------------------
extern "C" void kernel_launch(void* const* d_in, const int* in_sizes, int n_in,
                              void* d_out, int out_size) {
    const float* x       = (const float*)d_in[0];
    const float* in_geo  = (const float*)d_in[1];
    const float* in_box  = (const float*)d_in[2];
    const float* in_lin  = (const float*)d_in[3];
    const float* lay_geo = (const float*)d_in[4];
    const float* lay_box = (const float*)d_in[5];
    const float* lay_lin = (const float*)d_in[6];
    const float* dense_w = (const float*)d_in[7];
    const float* dense_b = (const float*)d_in[8];

    float* out    = (float*)d_out;
    float* logits = out;
    float* feat   = out + BATCH * NOUT;

    float *mixed_p, *x_p, *pool_p;
    cudaGetSymbolAddress((void**)&mixed_p, g_mixed);
    cudaGetSymbolAddress((void**)&x_p,     g_x);
    cudaGetSymbolAddress((void**)&pool_p,  g_pool);

    const int smem64  = 2 * 32 * BPITCH * 4;   // 34816
    const int smem128 = 2 * 64 * BPITCH * 4;   // 69632
    cudaFuncSetAttribute(mix_gemm_mma<64>,  cudaFuncAttributeMaxDynamicSharedMemorySize, smem64);
    cudaFuncSetAttribute(mix_gemm_mma<128>, cudaFuncAttributeMaxDynamicSharedMemorySize, smem128);

    // prep: A fragments + pool zero (1 launch), border zeros
    prep_all<<<(1024 + 4 * 2048 + 255) / 256, 256>>>(in_lin, lay_lin, pool_p);
    border_init<<<BATCH * CH, 128>>>(mixed_p);

    dim3 ggrid(HW / 128, BATCH);          // (72, 16)
    dim3 sgrid(HW / 256, CH, BATCH);      // (36, 128, 16)

    // input layer (K=64, no residual) — GEMM reads fp32 input directly
    mix_gemm_mma<64><<<ggrid, 256, smem64>>>(x, mixed_p, 0);
    sample_kernel<<<sgrid, 256>>>(mixed_p, in_geo, in_box, nullptr, x_p, 0, pool_p);

    // 4 residual layers (K=128)
    for (int i = 0; i < 4; i++) {
        mix_gemm_mma<128><<<ggrid, 256, smem128>>>(x_p, mixed_p, i + 1);
        bool last = (i == 3);
        float* dst = last ? feat : x_p;
        sample_kernel<<<sgrid, 256>>>(mixed_p, lay_geo + (size_t)i * CH * 6,
                                      lay_box + (size_t)i * CH * 6, x_p, dst,
                                      last ? 1 : 0, pool_p);
    }

    dense_kernel<<<(BATCH * NOUT + 255) / 256, 256>>>(pool_p, dense_w, dense_b, logits);
}

// round 14
// speedup vs baseline: 1.3008x; 1.1537x over previous
#include <cuda_runtime.h>
#include <cuda_bf16.h>
#include <cstdint>
#include <cstddef>

#define CH   128
#define HH   96
#define WW   96
#define HW   9216          // 96*96
#define BATCH 16
#define NOUT 1000

// Padded mixed layout: data pixel (h,w) -> plane[(h+1)*PP + (w+2)]
#define PP    104
#define PPH   100
#define PLANE (PP * PPH)   // 10400 floats per (b,c) plane

// ---------------------------------------------------------------------------
// Scratch (device globals — no runtime allocation allowed)
// ---------------------------------------------------------------------------
__device__ float g_mixedA[(size_t)BATCH * CH * PLANE];  // 85.2 MB (padded)
__device__ float g_mixedB[(size_t)BATCH * CH * PLANE];  // 85.2 MB (padded)
__device__ float g_x[(size_t)BATCH * CH * HW];          // 75.5 MB
__device__ float g_pool[BATCH * CH];
// A fragments in mma register order: [slot][kstep(8)][mtile(8)][lane(32)]
__device__ uint4 g_afh[5 * 8 * 8 * 32];
__device__ uint4 g_afl[5 * 8 * 8 * 32];

// ---------------------------------------------------------------------------
__device__ __forceinline__ unsigned short bfbits(float x) {
    return __bfloat16_as_ushort(__float2bfloat16_rn(x));
}
__device__ __forceinline__ float bfval(float x) {
    return __bfloat162float(__float2bfloat16_rn(x));
}
__device__ __forceinline__ unsigned int pack2(unsigned short lo, unsigned short hi) {
    return (unsigned int)lo | ((unsigned int)hi << 16);
}
__device__ __forceinline__ void mma_bf16(float* d, uint4 a,
                                         unsigned int b0, unsigned int b1) {
    asm volatile(
        "mma.sync.aligned.m16n8k16.row.col.f32.bf16.bf16.f32 "
        "{%0,%1,%2,%3}, {%4,%5,%6,%7}, {%8,%9}, {%0,%1,%2,%3};"
        : "+f"(d[0]), "+f"(d[1]), "+f"(d[2]), "+f"(d[3])
        : "r"(a.x), "r"(a.y), "r"(a.z), "r"(a.w), "r"(b0), "r"(b1));
}

// ---------------------------------------------------------------------------
// prep_all: pack all 5 lin matrices into mma A-fragments; zero pool accum.
// ---------------------------------------------------------------------------
__global__ void prep_all(const float* __restrict__ in_lin,
                         const float* __restrict__ lay_lin,
                         float* __restrict__ pool) {
    int t = blockIdx.x * 256 + threadIdx.x;
    if (t < BATCH * CH) pool[t] = 0.f;

    const float* lin;
    int slot, K, local;
    if (t < 1024) {
        slot = 0; K = 64; local = t; lin = in_lin;
    } else if (t < 1024 + 4 * 2048) {
        int j = t - 1024;
        slot = 1 + j / 2048; K = 128; local = j & 2047;
        lin = lay_lin + (size_t)(slot - 1) * CH * CH;
    } else return;

    int lane  = local & 31;
    int mtile = (local >> 5) & 7;
    int ks    = local >> 8;
    int m0 = mtile * 16 + (lane >> 2);
    int k0 = ks * 16 + (lane & 3) * 2;

    float a00 = lin[(size_t)m0 * K + k0],           a01 = lin[(size_t)m0 * K + k0 + 1];
    float a10 = lin[(size_t)(m0 + 8) * K + k0],     a11 = lin[(size_t)(m0 + 8) * K + k0 + 1];
    float a02 = lin[(size_t)m0 * K + k0 + 8],       a03 = lin[(size_t)m0 * K + k0 + 9];
    float a12 = lin[(size_t)(m0 + 8) * K + k0 + 8], a13 = lin[(size_t)(m0 + 8) * K + k0 + 9];

    uint4 h, l;
    h.x = pack2(bfbits(a00), bfbits(a01));
    h.y = pack2(bfbits(a10), bfbits(a11));
    h.z = pack2(bfbits(a02), bfbits(a03));
    h.w = pack2(bfbits(a12), bfbits(a13));
    l.x = pack2(bfbits(a00 - bfval(a00)), bfbits(a01 - bfval(a01)));
    l.y = pack2(bfbits(a10 - bfval(a10)), bfbits(a11 - bfval(a11)));
    l.z = pack2(bfbits(a02 - bfval(a02)), bfbits(a03 - bfval(a03)));
    l.w = pack2(bfbits(a12 - bfval(a12)), bfbits(a13 - bfval(a13)));

    int off = ((slot * 8 + ks) * 8 + mtile) * 32 + lane;
    g_afh[off] = h;
    g_afl[off] = l;
}

// ---------------------------------------------------------------------------
// border_init: zero guard borders of both padded mixed buffers.
// ---------------------------------------------------------------------------
__global__ void border_init(float* __restrict__ mA, float* __restrict__ mB) {
    float* pl = ((blockIdx.x & 1) ? mB : mA) + (size_t)(blockIdx.x >> 1) * PLANE;
    for (int i = threadIdx.x; i < 4 * PP + 4 * 96; i += 128) {
        int idx;
        if (i < 4 * PP) {
            int r4 = i / PP;
            int rr = (r4 == 0) ? 0 : (96 + r4);
            idx = rr * PP + (i - r4 * PP);
        } else {
            int j  = i - 4 * PP;
            int c4 = j / 96;
            int col = (c4 < 2) ? c4 : (96 + c4);
            idx = (1 + (j - c4 * 96)) * PP + col;
        }
        pl[idx] = 0.f;
    }
}

// ---------------------------------------------------------------------------
// GEMM mainloop + padded epilogue, shared by gemm0 and the fused kernel.
// Requires Bh/Bl smem tiles filled (pair-packed bf16, pitch BPITCH).
// ---------------------------------------------------------------------------
#define BPITCH 136
template<int K>
__device__ __forceinline__ void gemm_core(const unsigned int* Bh,
                                          const unsigned int* Bl,
                                          float* outp, int b, int pbase,
                                          int slot, int lane, int warp) {
    constexpr int KS = K / 16;
    const int wm = warp >> 2;
    const int wn = warp & 3;

    float acc[4][4][4];
#pragma unroll
    for (int t = 0; t < 4; t++)
#pragma unroll
        for (int u = 0; u < 4; u++)
#pragma unroll
            for (int r = 0; r < 4; r++) acc[t][u][r] = 0.f;

    const uint4* afh = g_afh + (size_t)slot * 8 * 8 * 32;
    const uint4* afl = g_afl + (size_t)slot * 8 * 8 * 32;

#pragma unroll
    for (int ks = 0; ks < KS; ks++) {
        unsigned int bh0[4], bh1[4], bl0[4], bl1[4];
        const int r0 = (ks * 8 + (lane & 3)) * BPITCH;
        const int r1 = r0 + 4 * BPITCH;
#pragma unroll
        for (int u = 0; u < 4; u++) {
            int n = wn * 32 + u * 8 + (lane >> 2);
            bh0[u] = Bh[r0 + n]; bh1[u] = Bh[r1 + n];
            bl0[u] = Bl[r0 + n]; bl1[u] = Bl[r1 + n];
        }
#pragma unroll
        for (int t = 0; t < 4; t++) {
            uint4 ah = afh[(ks * 8 + wm * 4 + t) * 32 + lane];
            uint4 al = afl[(ks * 8 + wm * 4 + t) * 32 + lane];
#pragma unroll
            for (int u = 0; u < 4; u++) {
                mma_bf16(acc[t][u], ah, bh0[u], bh1[u]);
                mma_bf16(acc[t][u], ah, bl0[u], bl1[u]);
                mma_bf16(acc[t][u], al, bh0[u], bh1[u]);
            }
        }
    }

    float* mb = outp + (size_t)b * CH * PLANE;
#pragma unroll
    for (int t = 0; t < 4; t++) {
        int m0 = wm * 64 + t * 16 + (lane >> 2);
#pragma unroll
        for (int u = 0; u < 4; u++) {
            int p = pbase + wn * 32 + u * 8 + (lane & 3) * 2;
            int h = p / 96;
            int w = p - h * 96;
            size_t po = (size_t)(h + 1) * PP + (w + 2);
            *(float2*)(mb + (size_t)m0 * PLANE + po)       = make_float2(acc[t][u][0], acc[t][u][1]);
            *(float2*)(mb + (size_t)(m0 + 8) * PLANE + po) = make_float2(acc[t][u][2], acc[t][u][3]);
        }
    }
}

// ---------------------------------------------------------------------------
// gemm0: input layer (K=64), reads fp32 x directly (R13 proven loader).
// ---------------------------------------------------------------------------
template<int K>
__global__ __launch_bounds__(256, 2)
void mix_gemm_mma(const float* __restrict__ xin,
                  float* __restrict__ outp, int slot) {
    constexpr int K2 = K / 2;
    extern __shared__ unsigned int smb[];
    unsigned int* Bh = smb;
    unsigned int* Bl = smb + K2 * BPITCH;

    const int b     = blockIdx.y;
    const int pbase = blockIdx.x * 128;
    const int tid   = threadIdx.x;

    {
        const float* xb = xin + (size_t)b * K * HW + pbase;
        for (int i = tid; i < K2 * 128; i += 256) {
            int k2 = i >> 7, p = i & 127;
            float v0 = xb[(size_t)(2 * k2) * HW + p];
            float v1 = xb[(size_t)(2 * k2 + 1) * HW + p];
            unsigned short h0 = bfbits(v0), h1 = bfbits(v1);
            Bh[k2 * BPITCH + p] = pack2(h0, h1);
            Bl[k2 * BPITCH + p] = pack2(
                bfbits(v0 - __bfloat162float(__ushort_as_bfloat16(h0))),
                bfbits(v1 - __bfloat162float(__ushort_as_bfloat16(h1))));
        }
    }
    __syncthreads();
    gemm_core<K>(Bh, Bl, outp, b, pbase, slot, tid & 31, tid >> 5);
}

// ---------------------------------------------------------------------------
// Fused kernel: sample (maskless padded gather + box weight + residual) for
// all 128 channels of this block's 128 pixels -> writes fp32 x, packs bf16
// hi/lo into smem B tile -> GEMM -> writes next padded mixed.
// Warp w samples channels [w*16, w*16+16), lanes = 32 consecutive pixels.
// ---------------------------------------------------------------------------
__global__ __launch_bounds__(256, 2)
void fused_sample_gemm(const float* __restrict__ mixin,
                       float* __restrict__ mixout,
                       const float* __restrict__ geo,
                       const float* __restrict__ box,
                       const float* __restrict__ resid,   // null for layer 0
                       float* __restrict__ xout,
                       int slot) {
    extern __shared__ unsigned int smb[];
    unsigned int* Bh = smb;
    unsigned int* Bl = smb + 64 * BPITCH;
    unsigned short* BhS = (unsigned short*)Bh;
    unsigned short* BlS = (unsigned short*)Bl;

    const int b     = blockIdx.y;
    const int pbase = blockIdx.x * 128;
    const int tid   = threadIdx.x;
    const int lane  = tid & 31;
    const int warp  = tid >> 5;

    // ---- sample phase ----
#pragma unroll 1
    for (int ci = 0; ci < 16; ci++) {
        const int c = warp * 16 + ci;
        const float* g = geo + c * 6;
        const float g0 = __ldg(g + 0), g1 = __ldg(g + 1), g2 = __ldg(g + 2);
        const float g3 = __ldg(g + 3), g4 = __ldg(g + 4), g5 = __ldg(g + 5);
        const float* bq = box + c * 6;
        const float q0 = __ldg(bq + 0), q1 = __ldg(bq + 1), q2 = __ldg(bq + 2);
        const float q3 = __ldg(bq + 3), q4 = __ldg(bq + 4), q5 = __ldg(bq + 5);

        const float* plane = mixin + ((size_t)b * CH + c) * PLANE;
        const int k2   = c >> 1;
        const int half = c & 1;

#pragma unroll
        for (int pg = 0; pg < 4; pg++) {
            const int pl = pg * 32 + lane;          // 0..127
            const int p  = pbase + pl;
            const int h  = p / 96;
            const int w  = p - h * 96;
            const float gxc = (w + 0.5f) * (2.0f / WW) - 1.0f;
            const float gyc = (h + 0.5f) * (2.0f / HH) - 1.0f;

            float ix = (g0 * gxc + g1 * gyc + g2) * 48.f + 47.5f;
            float iy = (g3 * gxc + g4 * gyc + g5) * 48.f + 47.5f;
            ix = fminf(fmaxf(ix, -1.0f), 96.0f);
            iy = fminf(fmaxf(iy, -1.0f), 96.0f);
            float fx0 = floorf(ix), fy0 = floorf(iy);
            int   x0 = (int)fx0, y0 = (int)fy0;
            float wx1 = ix - fx0, wy1 = iy - fy0;
            float wx0 = 1.0f - wx1, wy0 = 1.0f - wy1;

            const float* tapb = plane + (size_t)(y0 + 1) * PP + (x0 + 2);
            float t00 = tapb[0],  t01 = tapb[1];
            float t10 = tapb[PP], t11 = tapb[PP + 1];
            float s = wy0 * fmaf(wx0, t00, wx1 * t01)
                    + wy1 * fmaf(wx0, t10, wx1 * t11);

            float bix = (q0 * gxc + q1 * gyc + q2) * 48.f + 47.5f;
            float biy = (q3 * gxc + q4 * gyc + q5) * 48.f + 47.5f;
            float bfx0 = floorf(bix), bfy0 = floorf(biy);
            int   bx0 = (int)bfx0, by0 = (int)bfy0;
            float bwx1 = bix - bfx0, bwy1 = biy - bfy0;
            float sx = (((unsigned)bx0       < (unsigned)WW) ? (1.f - bwx1) : 0.f)
                     + (((unsigned)(bx0 + 1) < (unsigned)WW) ? bwx1         : 0.f);
            float sy = (((unsigned)by0       < (unsigned)HH) ? (1.f - bwy1) : 0.f)
                     + (((unsigned)(by0 + 1) < (unsigned)HH) ? bwy1         : 0.f);

            const size_t idx = ((size_t)b * CH + c) * HW + p;
            float v = s * (sx * sy);
            if (resid) v += resid[idx];
            xout[idx] = v;

            unsigned short hb = bfbits(v);
            unsigned short lb = bfbits(v - __bfloat162float(__ushort_as_bfloat16(hb)));
            BhS[2 * (k2 * BPITCH + pl) + half] = hb;
            BlS[2 * (k2 * BPITCH + pl) + half] = lb;
        }
    }
    __syncthreads();

    // ---- GEMM phase ----
    gemm_core<128>(Bh, Bl, mixout, b, pbase, slot, lane, warp);
}

// ---------------------------------------------------------------------------
// Final standalone sample (R13 proven, 78.5us): feat write + fused pool.
// ---------------------------------------------------------------------------
__global__ void sample_kernel(const float* __restrict__ mixedp,
                              const float* __restrict__ geo,
                              const float* __restrict__ box,
                              const float* __restrict__ resid,
                              float* __restrict__ out,
                              float* __restrict__ pool) {
    const int c = blockIdx.y;
    const int b = blockIdx.z;
    const int p = blockIdx.x * 256 + threadIdx.x;
    const int h = p / WW;
    const int w = p - h * WW;

    const float gxc = (w + 0.5f) * (2.0f / WW) - 1.0f;
    const float gyc = (h + 0.5f) * (2.0f / HH) - 1.0f;

    const float* g = geo + c * 6;
    float ix = (__ldg(g + 0) * gxc + __ldg(g + 1) * gyc + __ldg(g + 2)) * 48.f + 47.5f;
    float iy = (__ldg(g + 3) * gxc + __ldg(g + 4) * gyc + __ldg(g + 5)) * 48.f + 47.5f;
    ix = fminf(fmaxf(ix, -1.0f), 96.0f);
    iy = fminf(fmaxf(iy, -1.0f), 96.0f);
    float fx0 = floorf(ix), fy0 = floorf(iy);
    int   x0 = (int)fx0, y0 = (int)fy0;
    float wx1 = ix - fx0, wy1 = iy - fy0;
    float wx0 = 1.0f - wx1, wy0 = 1.0f - wy1;

    const float* tapb = mixedp + ((size_t)b * CH + c) * PLANE
                      + (size_t)(y0 + 1) * PP + (x0 + 2);
    float t00 = tapb[0],  t01 = tapb[1];
    float t10 = tapb[PP], t11 = tapb[PP + 1];
    float s = wy0 * fmaf(wx0, t00, wx1 * t01)
            + wy1 * fmaf(wx0, t10, wx1 * t11);

    const float* bx = box + c * 6;
    float bix = (__ldg(bx + 0) * gxc + __ldg(bx + 1) * gyc + __ldg(bx + 2)) * 48.f + 47.5f;
    float biy = (__ldg(bx + 3) * gxc + __ldg(bx + 4) * gyc + __ldg(bx + 5)) * 48.f + 47.5f;
    float bfx0 = floorf(bix), bfy0 = floorf(biy);
    int   bx0 = (int)bfx0, by0 = (int)bfy0;
    float bwx1 = bix - bfx0, bwy1 = biy - bfy0;
    float sx = (((unsigned)bx0       < (unsigned)WW) ? (1.f - bwx1) : 0.f)
             + (((unsigned)(bx0 + 1) < (unsigned)WW) ? bwx1         : 0.f);
    float sy = (((unsigned)by0       < (unsigned)HH) ? (1.f - bwy1) : 0.f)
             + (((unsigned)(by0 + 1) < (unsigned)HH) ? bwy1         : 0.f);

    const size_t idx = ((size_t)b * CH + c) * HW + p;
    float v = s * (sx * sy);
    if (resid) v += resid[idx];
    out[idx] = v;

    float r = v;
    for (int o = 16; o > 0; o >>= 1) r += __shfl_down_sync(0xffffffffu, r, o);
    __shared__ float sm[8];
    if ((threadIdx.x & 31) == 0) sm[threadIdx.x >> 5] = r;
    __syncthreads();
    if (threadIdx.x == 0) {
        float tt = 0.f;
        for (int i = 0; i < 8; i++) tt += sm[i];
        atomicAdd(pool + b * CH + c, tt);
    }
}

// ---------------------------------------------------------------------------
__global__ void dense_kernel(const float* __restrict__ pooled,
                             const float* __restrict__ dw,
                             const float* __restrict__ db,
                             float* __restrict__ logits) {
    int gid = blockIdx.x * 256 + threadIdx.x;
    if (gid >= BATCH * NOUT) return;
    int o = gid % NOUT;
    int b = gid / NOUT;
    const float* pr = pooled + b * CH;
    const float* wr = dw + (size_t)o * CH;
    float s = 0.f;
#pragma unroll 16
    for (int c = 0; c < CH; c++) s = fmaf(pr[c], wr[c], s);
    logits[gid] = s * (1.0f / HW) + db[o];
}

// ---------------------------------------------------------------------------
extern "C" void kernel_launch(void* const* d_in, const int* in_sizes, int n_in,
                              void* d_out, int out_size) {
    const float* x       = (const float*)d_in[0];
    const float* in_geo  = (const float*)d_in[1];
    const float* in_box  = (const float*)d_in[2];
    const float* in_lin  = (const float*)d_in[3];
    const float* lay_geo = (const float*)d_in[4];
    const float* lay_box = (const float*)d_in[5];
    const float* lay_lin = (const float*)d_in[6];
    const float* dense_w = (const float*)d_in[7];
    const float* dense_b = (const float*)d_in[8];

    float* out    = (float*)d_out;
    float* logits = out;
    float* feat   = out + BATCH * NOUT;

    float *mA, *mB, *x_p, *pool_p;
    cudaGetSymbolAddress((void**)&mA,     g_mixedA);
    cudaGetSymbolAddress((void**)&mB,     g_mixedB);
    cudaGetSymbolAddress((void**)&x_p,    g_x);
    cudaGetSymbolAddress((void**)&pool_p, g_pool);

    const int smem64  = 2 * 32 * BPITCH * 4;   // 34816
    const int smem128 = 2 * 64 * BPITCH * 4;   // 69632
    cudaFuncSetAttribute(mix_gemm_mma<64>, cudaFuncAttributeMaxDynamicSharedMemorySize, smem64);
    cudaFuncSetAttribute(fused_sample_gemm, cudaFuncAttributeMaxDynamicSharedMemorySize, smem128);

    prep_all<<<(1024 + 4 * 2048 + 255) / 256, 256>>>(in_lin, lay_lin, pool_p);
    border_init<<<2 * BATCH * CH, 128>>>(mA, mB);

    dim3 ggrid(HW / 128, BATCH);          // (72, 16)
    dim3 sgrid(HW / 256, CH, BATCH);      // (36, 128, 16)

    // gemm0: mixedA = in_lin @ x_raw
    mix_gemm_mma<64><<<ggrid, 256, smem64>>>(x, mA, 0);

    // F0: x1 = sample(mixedA; in_geo/in_box), mixedB = lay_lin0 @ x1
    fused_sample_gemm<<<ggrid, 256, smem128>>>(mA, mB, in_geo, in_box,
                                               nullptr, x_p, 1);
    // F1..F3: x_{i+1} = sample(mixed; lay_geo[i-1]) + x_i ; mixed' = lin @ x
    fused_sample_gemm<<<ggrid, 256, smem128>>>(mB, mA,
        lay_geo + 0 * CH * 6, lay_box + 0 * CH * 6, x_p, x_p, 2);
    fused_sample_gemm<<<ggrid, 256, smem128>>>(mA, mB,
        lay_geo + 1 * CH * 6, lay_box + 1 * CH * 6, x_p, x_p, 3);
    fused_sample_gemm<<<ggrid, 256, smem128>>>(mB, mA,
        lay_geo + 2 * CH * 6, lay_box + 2 * CH * 6, x_p, x_p, 4);

    // final sample: feat = sample(mixedA; lay_geo[3]) + x4, fused pool
    sample_kernel<<<sgrid, 256>>>(mA, lay_geo + 3 * CH * 6,
                                  lay_box + 3 * CH * 6, x_p, feat, pool_p);

    dense_kernel<<<(BATCH * NOUT + 255) / 256, 256>>>(pool_p, dense_w, dense_b, logits);
}

// round 15
// speedup vs baseline: 1.3515x; 1.0390x over previous
#include <cuda_runtime.h>
#include <cuda_bf16.h>
#include <cstdint>
#include <cstddef>

#define CH   128
#define HH   96
#define WW   96
#define HW   9216          // 96*96
#define BATCH 16
#define NOUT 1000

// Padded mixed layout: data pixel (h,w) -> plane[(h+1)*PP + (w+2)]
#define PP    104
#define PPH   100
#define PLANE (PP * PPH)   // 10400 floats per (b,c) plane

// ---------------------------------------------------------------------------
// Scratch (device globals — no runtime allocation allowed)
// ---------------------------------------------------------------------------
__device__ float g_mixedA[(size_t)BATCH * CH * PLANE];  // 85.2 MB (padded)
__device__ float g_mixedB[(size_t)BATCH * CH * PLANE];  // 85.2 MB (padded)
__device__ float g_x[(size_t)BATCH * CH * HW];          // 75.5 MB
__device__ float g_pool[BATCH * CH];
// A fragments in mma register order: [slot][kstep(8)][mtile(8)][lane(32)]
__device__ uint4 g_afh[5 * 8 * 8 * 32];
__device__ uint4 g_afl[5 * 8 * 8 * 32];

// ---------------------------------------------------------------------------
__device__ __forceinline__ unsigned short bfbits(float x) {
    return __bfloat16_as_ushort(__float2bfloat16_rn(x));
}
__device__ __forceinline__ float bfval(float x) {
    return __bfloat162float(__float2bfloat16_rn(x));
}
__device__ __forceinline__ unsigned int pack2(unsigned short lo, unsigned short hi) {
    return (unsigned int)lo | ((unsigned int)hi << 16);
}
__device__ __forceinline__ void mma_bf16(float* d, uint4 a,
                                         unsigned int b0, unsigned int b1) {
    asm volatile(
        "mma.sync.aligned.m16n8k16.row.col.f32.bf16.bf16.f32 "
        "{%0,%1,%2,%3}, {%4,%5,%6,%7}, {%8,%9}, {%0,%1,%2,%3};"
        : "+f"(d[0]), "+f"(d[1]), "+f"(d[2]), "+f"(d[3])
        : "r"(a.x), "r"(a.y), "r"(a.z), "r"(a.w), "r"(b0), "r"(b1));
}

// ---------------------------------------------------------------------------
// prep_all: pack all 5 lin matrices into mma A-fragments; zero pool accum.
// ---------------------------------------------------------------------------
__global__ void prep_all(const float* __restrict__ in_lin,
                         const float* __restrict__ lay_lin,
                         float* __restrict__ pool) {
    int t = blockIdx.x * 256 + threadIdx.x;
    if (t < BATCH * CH) pool[t] = 0.f;

    const float* lin;
    int slot, K, local;
    if (t < 1024) {
        slot = 0; K = 64; local = t; lin = in_lin;
    } else if (t < 1024 + 4 * 2048) {
        int j = t - 1024;
        slot = 1 + j / 2048; K = 128; local = j & 2047;
        lin = lay_lin + (size_t)(slot - 1) * CH * CH;
    } else return;

    int lane  = local & 31;
    int mtile = (local >> 5) & 7;
    int ks    = local >> 8;
    int m0 = mtile * 16 + (lane >> 2);
    int k0 = ks * 16 + (lane & 3) * 2;

    float a00 = lin[(size_t)m0 * K + k0],           a01 = lin[(size_t)m0 * K + k0 + 1];
    float a10 = lin[(size_t)(m0 + 8) * K + k0],     a11 = lin[(size_t)(m0 + 8) * K + k0 + 1];
    float a02 = lin[(size_t)m0 * K + k0 + 8],       a03 = lin[(size_t)m0 * K + k0 + 9];
    float a12 = lin[(size_t)(m0 + 8) * K + k0 + 8], a13 = lin[(size_t)(m0 + 8) * K + k0 + 9];

    uint4 h, l;
    h.x = pack2(bfbits(a00), bfbits(a01));
    h.y = pack2(bfbits(a10), bfbits(a11));
    h.z = pack2(bfbits(a02), bfbits(a03));
    h.w = pack2(bfbits(a12), bfbits(a13));
    l.x = pack2(bfbits(a00 - bfval(a00)), bfbits(a01 - bfval(a01)));
    l.y = pack2(bfbits(a10 - bfval(a10)), bfbits(a11 - bfval(a11)));
    l.z = pack2(bfbits(a02 - bfval(a02)), bfbits(a03 - bfval(a03)));
    l.w = pack2(bfbits(a12 - bfval(a12)), bfbits(a13 - bfval(a13)));

    int off = ((slot * 8 + ks) * 8 + mtile) * 32 + lane;
    g_afh[off] = h;
    g_afl[off] = l;
}

// ---------------------------------------------------------------------------
// border_init: zero guard borders of both padded mixed buffers.
// ---------------------------------------------------------------------------
__global__ void border_init(float* __restrict__ mA, float* __restrict__ mB) {
    float* pl = ((blockIdx.x & 1) ? mB : mA) + (size_t)(blockIdx.x >> 1) * PLANE;
    for (int i = threadIdx.x; i < 4 * PP + 4 * 96; i += 128) {
        int idx;
        if (i < 4 * PP) {
            int r4 = i / PP;
            int rr = (r4 == 0) ? 0 : (96 + r4);
            idx = rr * PP + (i - r4 * PP);
        } else {
            int j  = i - 4 * PP;
            int c4 = j / 96;
            int col = (c4 < 2) ? c4 : (96 + c4);
            idx = (1 + (j - c4 * 96)) * PP + col;
        }
        pl[idx] = 0.f;
    }
}

// ---------------------------------------------------------------------------
// GEMM mainloop + padded epilogue (R13/R14 proven).
// ---------------------------------------------------------------------------
#define BPITCH 136
template<int K>
__device__ __forceinline__ void gemm_core(const unsigned int* Bh,
                                          const unsigned int* Bl,
                                          float* outp, int b, int pbase,
                                          int slot, int lane, int warp) {
    constexpr int KS = K / 16;
    const int wm = warp >> 2;
    const int wn = warp & 3;

    float acc[4][4][4];
#pragma unroll
    for (int t = 0; t < 4; t++)
#pragma unroll
        for (int u = 0; u < 4; u++)
#pragma unroll
            for (int r = 0; r < 4; r++) acc[t][u][r] = 0.f;

    const uint4* afh = g_afh + (size_t)slot * 8 * 8 * 32;
    const uint4* afl = g_afl + (size_t)slot * 8 * 8 * 32;

#pragma unroll
    for (int ks = 0; ks < KS; ks++) {
        unsigned int bh0[4], bh1[4], bl0[4], bl1[4];
        const int r0 = (ks * 8 + (lane & 3)) * BPITCH;
        const int r1 = r0 + 4 * BPITCH;
#pragma unroll
        for (int u = 0; u < 4; u++) {
            int n = wn * 32 + u * 8 + (lane >> 2);
            bh0[u] = Bh[r0 + n]; bh1[u] = Bh[r1 + n];
            bl0[u] = Bl[r0 + n]; bl1[u] = Bl[r1 + n];
        }
#pragma unroll
        for (int t = 0; t < 4; t++) {
            uint4 ah = afh[(ks * 8 + wm * 4 + t) * 32 + lane];
            uint4 al = afl[(ks * 8 + wm * 4 + t) * 32 + lane];
#pragma unroll
            for (int u = 0; u < 4; u++) {
                mma_bf16(acc[t][u], ah, bh0[u], bh1[u]);
                mma_bf16(acc[t][u], ah, bl0[u], bl1[u]);
                mma_bf16(acc[t][u], al, bh0[u], bh1[u]);
            }
        }
    }

    float* mb = outp + (size_t)b * CH * PLANE;
#pragma unroll
    for (int t = 0; t < 4; t++) {
        int m0 = wm * 64 + t * 16 + (lane >> 2);
#pragma unroll
        for (int u = 0; u < 4; u++) {
            int p = pbase + wn * 32 + u * 8 + (lane & 3) * 2;
            int h = p / 96;
            int w = p - h * 96;
            size_t po = (size_t)(h + 1) * PP + (w + 2);
            *(float2*)(mb + (size_t)m0 * PLANE + po)       = make_float2(acc[t][u][0], acc[t][u][1]);
            *(float2*)(mb + (size_t)(m0 + 8) * PLANE + po) = make_float2(acc[t][u][2], acc[t][u][3]);
        }
    }
}

// ---------------------------------------------------------------------------
// gemm0: input layer (K=64), reads fp32 x directly.
// ---------------------------------------------------------------------------
template<int K>
__global__ __launch_bounds__(256, 2)
void mix_gemm_mma(const float* __restrict__ xin,
                  float* __restrict__ outp, int slot) {
    constexpr int K2 = K / 2;
    extern __shared__ unsigned int smb[];
    unsigned int* Bh = smb;
    unsigned int* Bl = smb + K2 * BPITCH;

    const int b     = blockIdx.y;
    const int pbase = blockIdx.x * 128;
    const int tid   = threadIdx.x;

    {
        const float* xb = xin + (size_t)b * K * HW + pbase;
        for (int i = tid; i < K2 * 128; i += 256) {
            int k2 = i >> 7, p = i & 127;
            float v0 = xb[(size_t)(2 * k2) * HW + p];
            float v1 = xb[(size_t)(2 * k2 + 1) * HW + p];
            unsigned short h0 = bfbits(v0), h1 = bfbits(v1);
            Bh[k2 * BPITCH + p] = pack2(h0, h1);
            Bl[k2 * BPITCH + p] = pack2(
                bfbits(v0 - __bfloat162float(__ushort_as_bfloat16(h0))),
                bfbits(v1 - __bfloat162float(__ushort_as_bfloat16(h1))));
        }
    }
    __syncthreads();
    gemm_core<K>(Bh, Bl, outp, b, pbase, slot, tid & 31, tid >> 5);
}

// ---------------------------------------------------------------------------
// Fused kernel: sample all 128 channels for this block's 128 pixels (warp =
// 16 channels, processed in PAIRS for MLP; pixel-group coords hoisted),
// residual add, fp32 x write, pair-packed bf16 into smem B tile -> GEMM.
// ---------------------------------------------------------------------------
__global__ __launch_bounds__(256, 2)
void fused_sample_gemm(const float* __restrict__ mixin,
                       float* __restrict__ mixout,
                       const float* __restrict__ geo,
                       const float* __restrict__ box,
                       const float* __restrict__ resid,   // null for layer 0
                       float* __restrict__ xout,
                       int slot) {
    extern __shared__ unsigned int smb[];
    unsigned int* Bh = smb;
    unsigned int* Bl = smb + 64 * BPITCH;

    const int b     = blockIdx.y;
    const int pbase = blockIdx.x * 128;
    const int tid   = threadIdx.x;
    const int lane  = tid & 31;
    const int warp  = tid >> 5;

    // hoisted per-pixel-group normalized coords (invariant across channels)
    float gxcv[4], gycv[4];
#pragma unroll
    for (int pg = 0; pg < 4; pg++) {
        int p = pbase + pg * 32 + lane;
        int h = p / 96;
        int w = p - h * 96;
        gxcv[pg] = (w + 0.5f) * (2.0f / WW) - 1.0f;
        gycv[pg] = (h + 0.5f) * (2.0f / HH) - 1.0f;
    }

    // ---- sample phase: 8 channel-pair iterations per warp ----
#pragma unroll 1
    for (int cj = 0; cj < 8; cj++) {
        const int c0 = warp * 16 + cj * 2;     // even channel; pair (c0, c0+1)
        const float* gA = geo + c0 * 6;
        const float* gB = gA + 6;
        const float a0 = __ldg(gA + 0), a1 = __ldg(gA + 1), a2 = __ldg(gA + 2);
        const float a3 = __ldg(gA + 3), a4 = __ldg(gA + 4), a5 = __ldg(gA + 5);
        const float b0 = __ldg(gB + 0), b1 = __ldg(gB + 1), b2 = __ldg(gB + 2);
        const float b3 = __ldg(gB + 3), b4 = __ldg(gB + 4), b5 = __ldg(gB + 5);
        const float* qA = box + c0 * 6;
        const float* qB = qA + 6;
        const float pa0 = __ldg(qA + 0), pa1 = __ldg(qA + 1), pa2 = __ldg(qA + 2);
        const float pa3 = __ldg(qA + 3), pa4 = __ldg(qA + 4), pa5 = __ldg(qA + 5);
        const float pb0 = __ldg(qB + 0), pb1 = __ldg(qB + 1), pb2 = __ldg(qB + 2);
        const float pb3 = __ldg(qB + 3), pb4 = __ldg(qB + 4), pb5 = __ldg(qB + 5);

        const float* plA = mixin + ((size_t)b * CH + c0) * PLANE;
        const float* plB = plA + PLANE;
        const int k2 = c0 >> 1;

#pragma unroll
        for (int pg = 0; pg < 4; pg++) {
            const int pl = pg * 32 + lane;
            const float gxc = gxcv[pg], gyc = gycv[pg];

            // channel A coords + taps
            float ixA = (a0 * gxc + a1 * gyc + a2) * 48.f + 47.5f;
            float iyA = (a3 * gxc + a4 * gyc + a5) * 48.f + 47.5f;
            ixA = fminf(fmaxf(ixA, -1.0f), 96.0f);
            iyA = fminf(fmaxf(iyA, -1.0f), 96.0f);
            float fxA = floorf(ixA), fyA = floorf(iyA);
            const float* tA = plA + (size_t)((int)fyA + 1) * PP + ((int)fxA + 2);
            // channel B coords + taps
            float ixB = (b0 * gxc + b1 * gyc + b2) * 48.f + 47.5f;
            float iyB = (b3 * gxc + b4 * gyc + b5) * 48.f + 47.5f;
            ixB = fminf(fmaxf(ixB, -1.0f), 96.0f);
            iyB = fminf(fmaxf(iyB, -1.0f), 96.0f);
            float fxB = floorf(ixB), fyB = floorf(iyB);
            const float* tB = plB + (size_t)((int)fyB + 1) * PP + ((int)fxB + 2);

            // issue all 8 tap loads up front
            float tA00 = tA[0],  tA01 = tA[1],  tA10 = tA[PP], tA11 = tA[PP + 1];
            float tB00 = tB[0],  tB01 = tB[1],  tB10 = tB[PP], tB11 = tB[PP + 1];

            float wxA1 = ixA - fxA, wyA1 = iyA - fyA;
            float wxA0 = 1.f - wxA1, wyA0 = 1.f - wyA1;
            float sA = wyA0 * fmaf(wxA0, tA00, wxA1 * tA01)
                     + wyA1 * fmaf(wxA0, tA10, wxA1 * tA11);
            float wxB1 = ixB - fxB, wyB1 = iyB - fyB;
            float wxB0 = 1.f - wxB1, wyB0 = 1.f - wyB1;
            float sB = wyB0 * fmaf(wxB0, tB00, wxB1 * tB01)
                     + wyB1 * fmaf(wxB0, tB10, wxB1 * tB11);

            // box weights (analytic)
            float bixA = (pa0 * gxc + pa1 * gyc + pa2) * 48.f + 47.5f;
            float biyA = (pa3 * gxc + pa4 * gyc + pa5) * 48.f + 47.5f;
            float bfxA = floorf(bixA), bfyA = floorf(biyA);
            int   bxA = (int)bfxA, byA = (int)bfyA;
            float bwxA = bixA - bfxA, bwyA = biyA - bfyA;
            float sxA = (((unsigned)bxA       < (unsigned)WW) ? (1.f - bwxA) : 0.f)
                      + (((unsigned)(bxA + 1) < (unsigned)WW) ? bwxA         : 0.f);
            float syA = (((unsigned)byA       < (unsigned)HH) ? (1.f - bwyA) : 0.f)
                      + (((unsigned)(byA + 1) < (unsigned)HH) ? bwyA         : 0.f);
            float bixB = (pb0 * gxc + pb1 * gyc + pb2) * 48.f + 47.5f;
            float biyB = (pb3 * gxc + pb4 * gyc + pb5) * 48.f + 47.5f;
            float bfxB = floorf(bixB), bfyB = floorf(biyB);
            int   bxB = (int)bfxB, byB = (int)bfyB;
            float bwxB = bixB - bfxB, bwyB = biyB - bfyB;
            float sxB = (((unsigned)bxB       < (unsigned)WW) ? (1.f - bwxB) : 0.f)
                      + (((unsigned)(bxB + 1) < (unsigned)WW) ? bwxB         : 0.f);
            float syB = (((unsigned)byB       < (unsigned)HH) ? (1.f - bwyB) : 0.f)
                      + (((unsigned)(byB + 1) < (unsigned)HH) ? bwyB         : 0.f);

            float vA = sA * (sxA * syA);
            float vB = sB * (sxB * syB);

            const size_t idxA = ((size_t)b * CH + c0) * HW + pbase + pl;
            if (resid) {
                vA += resid[idxA];
                vB += resid[idxA + HW];
            }
            xout[idxA]      = vA;
            xout[idxA + HW] = vB;

            unsigned short hA = bfbits(vA);
            unsigned short lA = bfbits(vA - __bfloat162float(__ushort_as_bfloat16(hA)));
            unsigned short hB = bfbits(vB);
            unsigned short lB = bfbits(vB - __bfloat162float(__ushort_as_bfloat16(hB)));
            Bh[k2 * BPITCH + pl] = pack2(hA, hB);   // one 32-bit smem store
            Bl[k2 * BPITCH + pl] = pack2(lA, lB);
        }
    }
    __syncthreads();

    // ---- GEMM phase ----
    gemm_core<128>(Bh, Bl, mixout, b, pbase, slot, lane, warp);
}

// ---------------------------------------------------------------------------
// Final standalone sample (R13 proven): feat write + fused pool.
// ---------------------------------------------------------------------------
__global__ void sample_kernel(const float* __restrict__ mixedp,
                              const float* __restrict__ geo,
                              const float* __restrict__ box,
                              const float* __restrict__ resid,
                              float* __restrict__ out,
                              float* __restrict__ pool) {
    const int c = blockIdx.y;
    const int b = blockIdx.z;
    const int p = blockIdx.x * 256 + threadIdx.x;
    const int h = p / WW;
    const int w = p - h * WW;

    const float gxc = (w + 0.5f) * (2.0f / WW) - 1.0f;
    const float gyc = (h + 0.5f) * (2.0f / HH) - 1.0f;

    const float* g = geo + c * 6;
    float ix = (__ldg(g + 0) * gxc + __ldg(g + 1) * gyc + __ldg(g + 2)) * 48.f + 47.5f;
    float iy = (__ldg(g + 3) * gxc + __ldg(g + 4) * gyc + __ldg(g + 5)) * 48.f + 47.5f;
    ix = fminf(fmaxf(ix, -1.0f), 96.0f);
    iy = fminf(fmaxf(iy, -1.0f), 96.0f);
    float fx0 = floorf(ix), fy0 = floorf(iy);
    int   x0 = (int)fx0, y0 = (int)fy0;
    float wx1 = ix - fx0, wy1 = iy - fy0;
    float wx0 = 1.0f - wx1, wy0 = 1.0f - wy1;

    const float* tapb = mixedp + ((size_t)b * CH + c) * PLANE
                      + (size_t)(y0 + 1) * PP + (x0 + 2);
    float t00 = tapb[0],  t01 = tapb[1];
    float t10 = tapb[PP], t11 = tapb[PP + 1];
    float s = wy0 * fmaf(wx0, t00, wx1 * t01)
            + wy1 * fmaf(wx0, t10, wx1 * t11);

    const float* bx = box + c * 6;
    float bix = (__ldg(bx + 0) * gxc + __ldg(bx + 1) * gyc + __ldg(bx + 2)) * 48.f + 47.5f;
    float biy = (__ldg(bx + 3) * gxc + __ldg(bx + 4) * gyc + __ldg(bx + 5)) * 48.f + 47.5f;
    float bfx0 = floorf(bix), bfy0 = floorf(biy);
    int   bx0 = (int)bfx0, by0 = (int)bfy0;
    float bwx1 = bix - bfx0, bwy1 = biy - bfy0;
    float sx = (((unsigned)bx0       < (unsigned)WW) ? (1.f - bwx1) : 0.f)
             + (((unsigned)(bx0 + 1) < (unsigned)WW) ? bwx1         : 0.f);
    float sy = (((unsigned)by0       < (unsigned)HH) ? (1.f - bwy1) : 0.f)
             + (((unsigned)(by0 + 1) < (unsigned)HH) ? bwy1         : 0.f);

    const size_t idx = ((size_t)b * CH + c) * HW + p;
    float v = s * (sx * sy);
    if (resid) v += resid[idx];
    out[idx] = v;

    float r = v;
    for (int o = 16; o > 0; o >>= 1) r += __shfl_down_sync(0xffffffffu, r, o);
    __shared__ float sm[8];
    if ((threadIdx.x & 31) == 0) sm[threadIdx.x >> 5] = r;
    __syncthreads();
    if (threadIdx.x == 0) {
        float tt = 0.f;
        for (int i = 0; i < 8; i++) tt += sm[i];
        atomicAdd(pool + b * CH + c, tt);
    }
}

// ---------------------------------------------------------------------------
__global__ void dense_kernel(const float* __restrict__ pooled,
                             const float* __restrict__ dw,
                             const float* __restrict__ db,
                             float* __restrict__ logits) {
    int gid = blockIdx.x * 256 + threadIdx.x;
    if (gid >= BATCH * NOUT) return;
    int o = gid % NOUT;
    int b = gid / NOUT;
    const float* pr = pooled + b * CH;
    const float* wr = dw + (size_t)o * CH;
    float s = 0.f;
#pragma unroll 16
    for (int c = 0; c < CH; c++) s = fmaf(pr[c], wr[c], s);
    logits[gid] = s * (1.0f / HW) + db[o];
}

// ---------------------------------------------------------------------------
extern "C" void kernel_launch(void* const* d_in, const int* in_sizes, int n_in,
                              void* d_out, int out_size) {
    const float* x       = (const float*)d_in[0];
    const float* in_geo  = (const float*)d_in[1];
    const float* in_box  = (const float*)d_in[2];
    const float* in_lin  = (const float*)d_in[3];
    const float* lay_geo = (const float*)d_in[4];
    const float* lay_box = (const float*)d_in[5];
    const float* lay_lin = (const float*)d_in[6];
    const float* dense_w = (const float*)d_in[7];
    const float* dense_b = (const float*)d_in[8];

    float* out    = (float*)d_out;
    float* logits = out;
    float* feat   = out + BATCH * NOUT;

    float *mA, *mB, *x_p, *pool_p;
    cudaGetSymbolAddress((void**)&mA,     g_mixedA);
    cudaGetSymbolAddress((void**)&mB,     g_mixedB);
    cudaGetSymbolAddress((void**)&x_p,    g_x);
    cudaGetSymbolAddress((void**)&pool_p, g_pool);

    const int smem64  = 2 * 32 * BPITCH * 4;   // 34816
    const int smem128 = 2 * 64 * BPITCH * 4;   // 69632
    cudaFuncSetAttribute(mix_gemm_mma<64>, cudaFuncAttributeMaxDynamicSharedMemorySize, smem64);
    cudaFuncSetAttribute(fused_sample_gemm, cudaFuncAttributeMaxDynamicSharedMemorySize, smem128);

    prep_all<<<(1024 + 4 * 2048 + 255) / 256, 256>>>(in_lin, lay_lin, pool_p);
    border_init<<<2 * BATCH * CH, 128>>>(mA, mB);

    dim3 ggrid(HW / 128, BATCH);          // (72, 16)
    dim3 sgrid(HW / 256, CH, BATCH);      // (36, 128, 16)

    // gemm0: mixedA = in_lin @ x_raw
    mix_gemm_mma<64><<<ggrid, 256, smem64>>>(x, mA, 0);

    // F0: x1 = sample(mixedA; in_geo/in_box), mixedB = lay_lin0 @ x1
    fused_sample_gemm<<<ggrid, 256, smem128>>>(mA, mB, in_geo, in_box,
                                               nullptr, x_p, 1);
    // F1..F3
    fused_sample_gemm<<<ggrid, 256, smem128>>>(mB, mA,
        lay_geo + 0 * CH * 6, lay_box + 0 * CH * 6, x_p, x_p, 2);
    fused_sample_gemm<<<ggrid, 256, smem128>>>(mA, mB,
        lay_geo + 1 * CH * 6, lay_box + 1 * CH * 6, x_p, x_p, 3);
    fused_sample_gemm<<<ggrid, 256, smem128>>>(mB, mA,
        lay_geo + 2 * CH * 6, lay_box + 2 * CH * 6, x_p, x_p, 4);

    // final sample: feat = sample(mixedA; lay_geo[3]) + x4, fused pool
    sample_kernel<<<sgrid, 256>>>(mA, lay_geo + 3 * CH * 6,
                                  lay_box + 3 * CH * 6, x_p, feat, pool_p);

    dense_kernel<<<(BATCH * NOUT + 255) / 256, 256>>>(pool_p, dense_w, dense_b, logits);
}